// round 9
// baseline (speedup 1.0000x reference)
#include <cuda_runtime.h>
#include <cuda_bf16.h>
#include <math.h>
#include <stdint.h>

#define Bn   8
#define NTn  8192
#define NSn  2048
#define CT   128
#define CS   256
#define CIN  384
#define CH   256
#define CO   128
#define Mtot (Bn * NTn)

// ---------------------------------------------------------------------------
// Device scratch (static — no runtime allocation)
// ---------------------------------------------------------------------------
__device__ __nv_bfloat16 g_comb_hi[(size_t)Mtot * CIN];
__device__ __nv_bfloat16 g_comb_lo[(size_t)Mtot * CIN];
__device__ __nv_bfloat16 g_hid_hi[(size_t)Mtot * CH];
__device__ __nv_bfloat16 g_hid_lo[(size_t)Mtot * CH];
__device__ __nv_bfloat16 g_w1t_hi[CH * CIN];
__device__ __nv_bfloat16 g_w1t_lo[CH * CIN];
__device__ __nv_bfloat16 g_w2t_hi[CO * CH];
__device__ __nv_bfloat16 g_w2t_lo[CO * CH];
__device__ __nv_bfloat16 g_wst_hi[CO * CIN];
__device__ __nv_bfloat16 g_wst_lo[CO * CIN];

// ---------------------------------------------------------------------------
// Helpers
// ---------------------------------------------------------------------------
__device__ __forceinline__ uint32_t smem_u32(const void* p) {
    uint32_t a;
    asm("{ .reg .u64 t; cvta.to.shared.u64 t, %1; cvt.u32.u64 %0, t; }" : "=r"(a) : "l"(p));
    return a;
}
#define CP16(smem_addr, gptr) \
    asm volatile("cp.async.cg.shared.global [%0], [%1], 16;" :: "r"(smem_addr), "l"(gptr))
#define CP_COMMIT() asm volatile("cp.async.commit_group;" ::: "memory")
#define CP_WAIT2()  asm volatile("cp.async.wait_group 2;" ::: "memory")
#define CP_WAIT1()  asm volatile("cp.async.wait_group 1;" ::: "memory")
#define CP_WAIT0()  asm volatile("cp.async.wait_group 0;" ::: "memory")

__device__ __forceinline__ void ldsm4(uint32_t& r0, uint32_t& r1, uint32_t& r2, uint32_t& r3,
                                      uint32_t a) {
    asm volatile("ldmatrix.sync.aligned.m8n8.x4.shared.b16 {%0,%1,%2,%3}, [%4];"
                 : "=r"(r0), "=r"(r1), "=r"(r2), "=r"(r3) : "r"(a));
}
__device__ __forceinline__ void mma16816(float* d, uint32_t a0, uint32_t a1, uint32_t a2,
                                         uint32_t a3, uint32_t b0, uint32_t b1) {
    asm volatile("mma.sync.aligned.m16n8k16.row.col.f32.bf16.bf16.f32 "
                 "{%0,%1,%2,%3}, {%4,%5,%6,%7}, {%8,%9}, {%0,%1,%2,%3};"
                 : "+f"(d[0]), "+f"(d[1]), "+f"(d[2]), "+f"(d[3])
                 : "r"(a0), "r"(a1), "r"(a2), "r"(a3), "r"(b0), "r"(b1));
}
__device__ __forceinline__ void split2(float v, __nv_bfloat16& h, __nv_bfloat16& l) {
    h = __float2bfloat16(v);
    l = __float2bfloat16(v - __bfloat162float(h));
}
__device__ __forceinline__ uint32_t pack2(__nv_bfloat16 a, __nv_bfloat16 b) {
    __nv_bfloat162 t; t.x = a; t.y = b;
    return *reinterpret_cast<uint32_t*>(&t);
}

// ---------------------------------------------------------------------------
// SMEM stage: 4 tensors [128 rows x 16 bf16], pitch 48 B (conflict-free ldsm)
// Stage = 4 * 128 * 48 = 24576 B; 4 stages = 96 KB
// ---------------------------------------------------------------------------
#define PITCH  48
#define TSIZE  (128 * PITCH)
#define T_AH   0
#define T_AL   (1 * TSIZE)
#define T_BH   (2 * TSIZE)
#define T_BL   (3 * TSIZE)
#define STAGE  (4 * TSIZE)
#define GSMEM  (4 * STAGE)

// Load one k16 chunk: 4 tensors x 128 rows x 32B. 256 thr x 4 cp.async.
__device__ __forceinline__ void load_stage(uint32_t st,
    const __nv_bfloat16* Ah, const __nv_bfloat16* Al,
    const __nv_bfloat16* Bh, const __nv_bfloat16* Bl,
    int ld, int k0, int tid)
{
    const __nv_bfloat16* gp[4] = {Ah, Al, Bh, Bl};
    const int r = tid >> 1, seg = tid & 1;
#pragma unroll
    for (int t = 0; t < 4; t++)
        CP16(st + t * TSIZE + r * PITCH + seg * 16, gp[t] + (size_t)r * ld + k0 + seg * 8);
    CP_COMMIT();
}

// One k16 chunk of MMAs: 3 split products
__device__ __forceinline__ void mma_stage(uint32_t st, int warp_m, int warp_n, int lane,
                                          float acc[2][8][4])
{
    const uint32_t arow0 = warp_m * 32 + (lane & 15);
    const uint32_t ahalf = (lane >> 4) * 16;
    const uint32_t brow  = warp_n * 64 + (lane & 7) + ((lane >> 4) << 3);
    const uint32_t bhalf = ((lane >> 3) & 1) * 16;
#pragma unroll
    for (int p = 0; p < 3; p++) {              // Ah*Bh, Ah*Bl, Al*Bh
        const uint32_t aoff = (p == 2) ? T_AL : T_AH;
        const uint32_t boff = (p == 1) ? T_BL : T_BH;
        uint32_t a[2][4];
#pragma unroll
        for (int mt = 0; mt < 2; mt++)
            ldsm4(a[mt][0], a[mt][1], a[mt][2], a[mt][3],
                  st + aoff + (arow0 + mt * 16) * PITCH + ahalf);
#pragma unroll
        for (int j = 0; j < 4; j++) {
            uint32_t b0, b1, b2, b3;
            ldsm4(b0, b1, b2, b3, st + boff + (brow + j * 16) * PITCH + bhalf);
            mma16816(acc[0][2*j+0], a[0][0], a[0][1], a[0][2], a[0][3], b0, b1);
            mma16816(acc[0][2*j+1], a[0][0], a[0][1], a[0][2], a[0][3], b2, b3);
            mma16816(acc[1][2*j+0], a[1][0], a[1][1], a[1][2], a[1][3], b0, b1);
            mma16816(acc[1][2*j+1], a[1][0], a[1][1], a[1][2], a[1][3], b2, b3);
        }
    }
}

// ---------------------------------------------------------------------------
// Weight prep
// ---------------------------------------------------------------------------
__global__ void prep_weights(const float* __restrict__ W1, const float* __restrict__ W2,
                             const float* __restrict__ Ws) {
    int i = blockIdx.x * blockDim.x + threadIdx.x;
    if (i < CH * CIN) {
        int n = i / CIN, k = i % CIN;
        split2(W1[(size_t)k * CH + n], g_w1t_hi[i], g_w1t_lo[i]);
    }
    if (i < CO * CH) {
        int n = i / CH, k = i % CH;
        split2(W2[(size_t)k * CO + n], g_w2t_hi[i], g_w2t_lo[i]);
    }
    if (i < CO * CIN) {
        int n = i / CIN, k = i % CIN;
        split2(Ws[(size_t)k * CO + n], g_wst_hi[i], g_wst_lo[i]);
    }
}

// ---------------------------------------------------------------------------
// KNN: 64 targets/CTA, 4-way source split, merge 12->3
// ---------------------------------------------------------------------------
__global__ __launch_bounds__(256) void knn_kernel(
    const float* __restrict__ x_t, const float* __restrict__ pos_t,
    const float* __restrict__ x_s, const float* __restrict__ pos_s)
{
    __shared__ float4 sp[NSn];
    __shared__ float  cd[64][12];
    __shared__ int    ci[64][12];
    __shared__ float  swt[64][3];
    __shared__ int    sit[64][3];

    const int b   = blockIdx.y;
    const int tid = threadIdx.x;

    const float* ps = pos_s + (size_t)b * NSn * 3;
    for (int j = tid; j < NSn; j += 256)
        sp[j] = make_float4(ps[3*j], ps[3*j+1], ps[3*j+2], 0.f);
    __syncthreads();

    const int tt = tid & 63, sq = tid >> 6;
    const int t0 = b * NTn + blockIdx.x * 64;
    const int t  = t0 + tt;
    const float tx = pos_t[3*t], ty = pos_t[3*t+1], tz = pos_t[3*t+2];

    float d0 = 3.4e38f, d1 = 3.4e38f, d2 = 3.4e38f;
    int   i0 = 0, i1 = 0, i2 = 0;
    const int jb = sq * 512;
#pragma unroll 4
    for (int j = jb; j < jb + 512; j++) {
        float4 s = sp[j];
        float dx = tx - s.x, dy = ty - s.y, dz = tz - s.z;
        float d  = fmaf(dx, dx, fmaf(dy, dy, dz * dz));
        if (d < d2) {
            if (d < d1) {
                d2 = d1; i2 = i1;
                if (d < d0) { d1 = d0; i1 = i0; d0 = d; i0 = j; }
                else        { d1 = d;  i1 = j; }
            } else { d2 = d; i2 = j; }
        }
    }
    cd[tt][sq*3+0] = d0; ci[tt][sq*3+0] = i0;
    cd[tt][sq*3+1] = d1; ci[tt][sq*3+1] = i1;
    cd[tt][sq*3+2] = d2; ci[tt][sq*3+2] = i2;
    __syncthreads();

    if (tid < 64) {
        float e0 = 3.4e38f, e1 = 3.4e38f, e2 = 3.4e38f;
        int   j0 = 0, j1 = 0, j2 = 0;
#pragma unroll
        for (int k = 0; k < 12; k++) {
            float d = cd[tid][k]; int ii = ci[tid][k];
            if (d < e2) {
                if (d < e1) {
                    e2 = e1; j2 = j1;
                    if (d < e0) { e1 = e0; j1 = j0; e0 = d; j0 = ii; }
                    else        { e1 = d;  j1 = ii; }
                } else { e2 = d; j2 = ii; }
            }
        }
        float w0 = 1.f / fmaxf(e0, 1e-16f);
        float w1 = 1.f / fmaxf(e1, 1e-16f);
        float w2 = 1.f / fmaxf(e2, 1e-16f);
        float inv = 1.f / (w0 + w1 + w2);
        swt[tid][0] = w0 * inv; swt[tid][1] = w1 * inv; swt[tid][2] = w2 * inv;
        sit[tid][0] = j0; sit[tid][1] = j1; sit[tid][2] = j2;
    }
    __syncthreads();

    const float* xsb = x_s + (size_t)b * NSn * CS;
    const int c = tid;
    for (int u = 0; u < 64; u++) {
        const int tg = t0 + u;
        float v = swt[u][0] * xsb[(size_t)sit[u][0] * CS + c]
                + swt[u][1] * xsb[(size_t)sit[u][1] * CS + c]
                + swt[u][2] * xsb[(size_t)sit[u][2] * CS + c];
        __nv_bfloat16 h, l;
        split2(v, h, l);
        g_comb_hi[(size_t)tg * CIN + CT + c] = h;
        g_comb_lo[(size_t)tg * CIN + CT + c] = l;
        if (c < CT) {
            split2(x_t[(size_t)tg * CT + c], h, l);
            g_comb_hi[(size_t)tg * CIN + c] = h;
            g_comb_lo[(size_t)tg * CIN + c] = l;
        }
    }
}

// ---------------------------------------------------------------------------
// Multistage mainloop driver: NC chunks, 4 stages, one sync per chunk.
// get_chunk(c, Ah, Al, Bh, Bl, ld, k0) supplies per-chunk pointers.
// ---------------------------------------------------------------------------
#define PIPE_WAIT(pend) do { \
    if ((pend) >= 2) { CP_WAIT2(); } \
    else if ((pend) == 1) { CP_WAIT1(); } \
    else { CP_WAIT0(); } \
} while (0)

// ---------------------------------------------------------------------------
// GEMM1: hid = relu(comb @ W1 + b1), M tile 128, N tile 128, K=384 (24 chunks)
// ---------------------------------------------------------------------------
__global__ __launch_bounds__(256, 2) void gemm1_kernel(const float* __restrict__ b1) {
    extern __shared__ char smem[];
    const uint32_t sb = smem_u32(smem);
    const int tid = threadIdx.x, lane = tid & 31, wid = tid >> 5;
    const int warp_m = wid >> 1, warp_n = wid & 1;
    const int bn = blockIdx.x * 128, bm = blockIdx.y * 128;
    const int NC = 24;

    const __nv_bfloat16* Ah = g_comb_hi + (size_t)bm * CIN;
    const __nv_bfloat16* Al = g_comb_lo + (size_t)bm * CIN;
    const __nv_bfloat16* Bh = g_w1t_hi + (size_t)bn * CIN;
    const __nv_bfloat16* Bl = g_w1t_lo + (size_t)bn * CIN;

    float acc[2][8][4] = {};

#pragma unroll
    for (int c = 0; c < 3; c++)
        load_stage(sb + c * STAGE, Ah, Al, Bh, Bl, CIN, c * 16, tid);

    for (int c = 0; c < NC; c++) {
        PIPE_WAIT(NC - 1 - c);
        __syncthreads();
        if (c + 3 < NC)
            load_stage(sb + ((c + 3) & 3) * STAGE, Ah, Al, Bh, Bl, CIN, (c + 3) * 16, tid);
        mma_stage(sb + (c & 3) * STAGE, warp_m, warp_n, lane, acc);
    }

    uint32_t* dh = (uint32_t*)g_hid_hi;
    uint32_t* dl = (uint32_t*)g_hid_lo;
#pragma unroll
    for (int mt = 0; mt < 2; mt++) {
#pragma unroll
        for (int nt = 0; nt < 8; nt++) {
            const int col = bn + warp_n * 64 + nt * 8 + (lane & 3) * 2;
            const float bb0 = __ldg(b1 + col), bb1 = __ldg(b1 + col + 1);
            const int row = bm + warp_m * 32 + mt * 16 + (lane >> 2);
#pragma unroll
            for (int h = 0; h < 2; h++) {
                const int r = row + h * 8;
                float v0 = fmaxf(acc[mt][nt][2*h+0] + bb0, 0.f);
                float v1 = fmaxf(acc[mt][nt][2*h+1] + bb1, 0.f);
                __nv_bfloat16 h0, l0, h1, l1;
                split2(v0, h0, l0);
                split2(v1, h1, l1);
                const size_t w = ((size_t)r * CH + col) >> 1;
                dh[w] = pack2(h0, h1);
                dl[w] = pack2(l0, l1);
            }
        }
    }
}

// ---------------------------------------------------------------------------
// GEMM2: out = relu(hid @ W2 + comb @ Ws + b2 + bs)
// Unified 40-chunk stream: 16 from hid/W2, 24 from comb/Ws. No mid-drain.
// ---------------------------------------------------------------------------
__device__ __forceinline__ void g2_load(uint32_t st, int c, int bm, int tid) {
    if (c < 16)
        load_stage(st, g_hid_hi + (size_t)bm * CH, g_hid_lo + (size_t)bm * CH,
                   g_w2t_hi, g_w2t_lo, CH, c * 16, tid);
    else
        load_stage(st, g_comb_hi + (size_t)bm * CIN, g_comb_lo + (size_t)bm * CIN,
                   g_wst_hi, g_wst_lo, CIN, (c - 16) * 16, tid);
}

__global__ __launch_bounds__(256, 2) void gemm2_kernel(
    const float* __restrict__ b2, const float* __restrict__ bs, float* __restrict__ out)
{
    extern __shared__ char smem[];
    const uint32_t sb = smem_u32(smem);
    const int tid = threadIdx.x, lane = tid & 31, wid = tid >> 5;
    const int warp_m = wid >> 1, warp_n = wid & 1;
    const int bm = blockIdx.x * 128;
    const int NC = 40;

    float acc[2][8][4] = {};

#pragma unroll
    for (int c = 0; c < 3; c++)
        g2_load(sb + c * STAGE, c, bm, tid);

    for (int c = 0; c < NC; c++) {
        PIPE_WAIT(NC - 1 - c);
        __syncthreads();
        if (c + 3 < NC)
            g2_load(sb + ((c + 3) & 3) * STAGE, c + 3, bm, tid);
        mma_stage(sb + (c & 3) * STAGE, warp_m, warp_n, lane, acc);
    }

#pragma unroll
    for (int mt = 0; mt < 2; mt++) {
#pragma unroll
        for (int nt = 0; nt < 8; nt++) {
            const int col = warp_n * 64 + nt * 8 + (lane & 3) * 2;
            const float bb0 = __ldg(b2 + col) + __ldg(bs + col);
            const float bb1 = __ldg(b2 + col + 1) + __ldg(bs + col + 1);
            const int row = bm + warp_m * 32 + mt * 16 + (lane >> 2);
#pragma unroll
            for (int h = 0; h < 2; h++) {
                const int r = row + h * 8;
                float2 v;
                v.x = fmaxf(acc[mt][nt][2*h+0] + bb0, 0.f);
                v.y = fmaxf(acc[mt][nt][2*h+1] + bb1, 0.f);
                *(float2*)&out[(size_t)r * CO + col] = v;
            }
        }
    }
}

// ---------------------------------------------------------------------------
extern "C" void kernel_launch(void* const* d_in, const int* in_sizes, int n_in,
                              void* d_out, int out_size)
{
    const float* x_t   = (const float*)d_in[0];
    const float* pos_t = (const float*)d_in[1];
    const float* x_s   = (const float*)d_in[3];
    const float* pos_s = (const float*)d_in[4];
    const float* W1    = (const float*)d_in[6];
    const float* b1    = (const float*)d_in[7];
    const float* W2    = (const float*)d_in[8];
    const float* b2    = (const float*)d_in[9];
    const float* Ws    = (const float*)d_in[10];
    const float* bs    = (const float*)d_in[11];
    float* out = (float*)d_out;

    cudaFuncSetAttribute(gemm1_kernel, cudaFuncAttributeMaxDynamicSharedMemorySize, GSMEM);
    cudaFuncSetAttribute(gemm2_kernel, cudaFuncAttributeMaxDynamicSharedMemorySize, GSMEM);

    prep_weights<<<(CH * CIN + 255) / 256, 256>>>(W1, W2, Ws);
    knn_kernel<<<dim3(NTn / 64, Bn), 256>>>(x_t, pos_t, x_s, pos_s);
    gemm1_kernel<<<dim3(2, Mtot / 128), 256, GSMEM>>>(b1);
    gemm2_kernel<<<Mtot / 128, 256, GSMEM>>>(b2, bs, out);
}